// round 15
// baseline (speedup 1.0000x reference)
#include <cuda_runtime.h>
#include <cuda_fp16.h>
#include <cstdint>

namespace {

constexpr int BB = 256, TT = 512, DD = 64, HH = 128, KC = 256;
constexpr int NROW = BB * TT;            // 131072 (b,t) rows

// g_pre[row][q][j]: q = 0 zpre(+bz), 1 rpre(+br), 2 xmpre(+bh), 3 dh
__device__ float  g_pre[(size_t)NROW * 4 * HH];            // 256 MB
__device__ __half g_act[(size_t)NROW * 192];               // [row][xt|m|d]
// B fragments in mma.m16n8k16 lane order: 448 frags x 32 lanes x uint2
__device__ uint2  g_wfrag[448 * 32];

__device__ __forceinline__ float2 mk2(float x, float y) { return make_float2(x, y); }

__device__ __forceinline__ void ffma2(float2& d, float2 a, float2 b) {
    asm("{\n\t"
        ".reg .b64 ra, rb, rd;\n\t"
        "mov.b64 ra, {%2, %3};\n\t"
        "mov.b64 rb, {%4, %5};\n\t"
        "mov.b64 rd, {%0, %1};\n\t"
        "fma.rn.f32x2 rd, ra, rb, rd;\n\t"
        "mov.b64 {%0, %1}, rd;\n\t"
        "}"
        : "+f"(d.x), "+f"(d.y)
        : "f"(a.x), "f"(a.y), "f"(b.x), "f"(b.y));
}

__device__ __forceinline__ unsigned pack_h2(float x, float y) {
    __half2 h = __floats2half2_rn(x, y);
    return *reinterpret_cast<unsigned*>(&h);
}
__device__ __forceinline__ float2 unpk(unsigned u) {
    return __half22float2(*reinterpret_cast<__half2*>(&u));
}

#define MMA16816(d0, d1, d2, d3, a0, a1, a2, a3, b0, b1)                     \
    asm volatile(                                                            \
        "mma.sync.aligned.m16n8k16.row.col.f32.f16.f16.f32 "                 \
        "{%0,%1,%2,%3}, {%4,%5,%6,%7}, {%8,%9}, {%0,%1,%2,%3};"              \
        : "+f"(d0), "+f"(d1), "+f"(d2), "+f"(d3)                             \
        : "r"(a0), "r"(a1), "r"(a2), "r"(a3), "r"(b0), "r"(b1))

// ===========================================================================
// P1: elementwise -> fp16 act matrix [row][ xt(64) | m(64) | d(64) ].
// ===========================================================================
__global__ void __launch_bounds__(256, 1) act_kernel(
    const float* __restrict__ inp,
    const float* __restrict__ Wgx, const float* __restrict__ bgx)
{
    const int row = blockIdx.x * 8 + (threadIdx.x >> 5);
    const int l   = threadIdx.x & 31;
    const int b = row >> 9, t = row & 511;
    const float* ib = inp + ((long)(b * 4) * TT + t) * DD;
    const long CH = (long)TT * DD;
    float2 x  = *(const float2*)(ib + 2 * l);
    float2 xl = *(const float2*)(ib + CH + 2 * l);
    float2 m  = *(const float2*)(ib + 2 * CH + 2 * l);
    float2 d  = *(const float2*)(ib + 3 * CH + 2 * l);
    float  g0 = __ldg(&Wgx[(2 * l) * DD + 2 * l]);
    float  g1 = __ldg(&Wgx[(2 * l + 1) * DD + 2 * l + 1]);
    float2 bx = *(const float2*)(bgx + 2 * l);
    float dx0 = __expf(-fmaxf(fmaf(d.x, g0, bx.x), 0.f));
    float dx1 = __expf(-fmaxf(fmaf(d.y, g1, bx.y), 0.f));
    float xt0 = m.x * x.x + (1.f - m.x) * (dx0 * xl.x);
    float xt1 = m.y * x.y + (1.f - m.y) * (dx1 * xl.y);
    __half2* ga = (__half2*)(g_act + (size_t)row * 192);
    ga[l]      = __floats2half2_rn(xt0, xt1);
    ga[32 + l] = __floats2half2_rn(m.x, m.y);
    ga[64 + l] = __floats2half2_rn(d.x, d.y);
}

// ===========================================================================
// P0: pack weights into mma B-fragment lane order (verified R11).
// ===========================================================================
__global__ void packw_kernel(const float* __restrict__ Wz,
                             const float* __restrict__ Wr,
                             const float* __restrict__ Wh,
                             const float* __restrict__ Wgh) {
    int idx = blockIdx.x * 256 + threadIdx.x;
    int fragIdx = idx >> 5, lane = idx & 31;
    if (fragIdx >= 448) return;
    int g = lane >> 2, t = lane & 3;
    uint2 v;
    if (fragIdx < 384) {
        int q   = fragIdx >> 7;
        int rem = fragIdx & 127;
        int jt = rem >> 3, kt = rem & 7;
        const float* W = (q == 0) ? Wz : (q == 1) ? Wr : Wh;
        int j = jt * 8 + g, k0 = kt * 16;
        auto src = [&](int k) {
            int col = (k < 64) ? k : k + 128;
            return W[j * KC + col];
        };
        v.x = pack_h2(src(k0 + 2 * t),     src(k0 + 2 * t + 1));
        v.y = pack_h2(src(k0 + 2 * t + 8), src(k0 + 2 * t + 9));
    } else {
        int rem = fragIdx - 384;
        int jt = rem >> 2, kt = rem & 3;
        int j = jt * 8 + g, k0 = kt * 16;
        v.x = pack_h2(Wgh[j * DD + k0 + 2 * t],     Wgh[j * DD + k0 + 2 * t + 1]);
        v.y = pack_h2(Wgh[j * DD + k0 + 2 * t + 8], Wgh[j * DD + k0 + 2 * t + 9]);
    }
    g_wfrag[fragIdx * 32 + lane] = v;
}

// ===========================================================================
// P2: HMMA GEMM (verified R11, ~90 us).
// ===========================================================================
constexpr int GS_ACT  = 0;
constexpr int GS_WF   = 51200;
constexpr int GS_BIAS = GS_WF + 114688;
constexpr int GEMM_SMEM = GS_BIAS + 512 * 4;

__global__ void __launch_bounds__(256, 1) gemm_kernel(
    const float* __restrict__ bz, const float* __restrict__ br,
    const float* __restrict__ bh, const float* __restrict__ bgh)
{
    extern __shared__ char sm[];
    __half* sact = (__half*)(sm + GS_ACT);
    uint2*  swf  = (uint2*)(sm + GS_WF);
    float*  sbias = (float*)(sm + GS_BIAS);

    const int tid = threadIdx.x;
    const int row0 = blockIdx.x * 128;

    for (int i = tid; i < 128 * 48; i += 256) {
        int r = i / 48, c = i - r * 48;
        uint2 v = *(const uint2*)(g_act + (size_t)(row0 + r) * 192 + c * 4);
        *(uint2*)(sact + r * 200 + c * 4) = v;
    }
    for (int i = tid; i < 448 * 32 / 2; i += 256)
        ((uint4*)swf)[i] = ((const uint4*)g_wfrag)[i];
    if (tid < 128) {
        sbias[tid] = bz[tid];       sbias[128 + tid] = br[tid];
        sbias[256 + tid] = bh[tid]; sbias[384 + tid] = bgh[tid];
    }
    __syncthreads();

    const int w = tid >> 5, lane = tid & 31;
    const int g = lane >> 2, t = lane & 3;
    const int arow = w * 16 + g;

    uint32_t A[12][4];
    #pragma unroll
    for (int kt = 0; kt < 12; ++kt) {
        int k0 = (kt < 8) ? kt * 16 : 128 + (kt - 8) * 16;
        const __half* p = sact + arow * 200 + k0 + 2 * t;
        A[kt][0] = *(const uint32_t*)(p);
        A[kt][1] = *(const uint32_t*)(p + 8 * 200);
        A[kt][2] = *(const uint32_t*)(p + 8);
        A[kt][3] = *(const uint32_t*)(p + 8 * 200 + 8);
    }

    for (int q = 0; q < 3; ++q) {
        #pragma unroll 4
        for (int jt = 0; jt < 16; ++jt) {
            float d0 = 0.f, d1 = 0.f, d2 = 0.f, d3 = 0.f;
            const uint2* wp = swf + (q * 128 + jt * 8) * 32 + lane;
            #pragma unroll
            for (int kt = 0; kt < 8; ++kt) {
                uint2 b = wp[kt * 32];
                MMA16816(d0, d1, d2, d3,
                         A[kt][0], A[kt][1], A[kt][2], A[kt][3], b.x, b.y);
            }
            int j0 = jt * 8 + 2 * t;
            float2 bb = *(const float2*)&sbias[q * 128 + j0];
            size_t base = (size_t)(row0 + arow) * 512 + q * 128 + j0;
            *(float2*)&g_pre[base]            = mk2(d0 + bb.x, d1 + bb.y);
            *(float2*)&g_pre[base + 8 * 512]  = mk2(d2 + bb.x, d3 + bb.y);
        }
    }
    #pragma unroll 4
    for (int jt = 0; jt < 16; ++jt) {
        float d0 = 0.f, d1 = 0.f, d2 = 0.f, d3 = 0.f;
        const uint2* wp = swf + (384 + jt * 4) * 32 + lane;
        #pragma unroll
        for (int kt = 0; kt < 4; ++kt) {
            uint2 b = wp[kt * 32];
            MMA16816(d0, d1, d2, d3,
                     A[8 + kt][0], A[8 + kt][1], A[8 + kt][2], A[8 + kt][3],
                     b.x, b.y);
        }
        int j0 = jt * 8 + 2 * t;
        float2 bb = *(const float2*)&sbias[384 + j0];
        size_t base = (size_t)(row0 + arow) * 512 + 384 + j0;
        *(float2*)&g_pre[base] =
            mk2(__expf(-fmaxf(d0 + bb.x, 0.f)), __expf(-fmaxf(d1 + bb.y, 0.f)));
        *(float2*)&g_pre[base + 8 * 512] =
            mk2(__expf(-fmaxf(d2 + bb.x, 0.f)), __expf(-fmaxf(d3 + bb.y, 0.f)));
    }
}

// ===========================================================================
// Scan v6: SIMT (R10 math, fp32 state) with 4-way K-split, NT=512.
// thread = (j = tid>>2, kq = tid&3); partials reduce via shfl.xor(1,2)
// within the 4-lane kq group.  Work is PARTITIONED (not duplicated):
// per-thread 96 FFMA2 + ~96 cvt; 4 warps/SMSP hide latency.
// Quarter arrays padded to 36 floats -> kq groups hit disjoint banks.
// ===========================================================================
__global__ void __launch_bounds__(512, 1) scan_kernel(
    const float* __restrict__ Wz, const float* __restrict__ Wr,
    const float* __restrict__ Wh,
    float* __restrict__ out)         // [B,T,H]
{
    __shared__ float hpre[2][4][36];   // [b][quarter][32 + pad]
    __shared__ float crh [2][4][36];

    const int tid = threadIdx.x;
    const int b0  = blockIdx.x * 2;
    const int j   = tid >> 2;        // output row 0..127
    const int kq  = tid & 3;         // K-quarter / batch (epi, kq<2)
    const bool epi = (kq < 2);

    // weight rows over h-region cols [64 + kq*32, +32)
    unsigned wz_[16], wr_[16], wh_[16];
    {
        const int koff = 64 + kq * 32;
        #pragma unroll
        for (int i = 0; i < 16; ++i) {
            float2 a = *(const float2*)&Wz[j * KC + koff + 2 * i];
            wz_[i] = pack_h2(a.x, a.y);
            float2 b = *(const float2*)&Wr[j * KC + koff + 2 * i];
            wr_[i] = pack_h2(b.x, b.y);
            float2 c = *(const float2*)&Wh[j * KC + koff + 2 * i];
            wh_[i] = pack_h2(c.x, c.y);
        }
    }
    for (int i = tid; i < 2 * 4 * 36; i += 512) {
        ((float*)hpre)[i] = 0.f;
        ((float*)crh)[i]  = 0.f;
    }

    // scratch stream for epi threads: batch kq, row j
    const size_t tb = ((size_t)(b0 + (kq & 1)) * TT) * 512 + j;
    // double buffer: p = tuple(t), n = tuple(t+1); reload n AFTER rotation
    float pz = 0.f, pr = 0.f, px = 0.f, pd = 0.f;
    float nz = 0.f, nr = 0.f, nx = 0.f, nd = 0.f;
    float hown = 0.f, zraw = 0.f;
    if (epi) {
        pz = g_pre[tb];
        pr = g_pre[tb + 128];
        px = g_pre[tb + 256];
        pd = g_pre[tb + 512 + 384];          // dh(1)
        nz = g_pre[tb + 512];
        nr = g_pre[tb + 512 + 128];
        nx = g_pre[tb + 512 + 256];
        nd = g_pre[tb + 1024 + 384];         // dh(2)
    }
    __syncthreads();

    for (int t = 0; t < TT; ++t) {
        // ---- stage A: z/r partials over K-quarter kq, both batches ----
        {
            float2 az0 = mk2(0.f,0.f), az1 = mk2(0.f,0.f);
            float2 ar0 = mk2(0.f,0.f), ar1 = mk2(0.f,0.f);
            #pragma unroll
            for (int i = 0; i < 8; ++i) {
                float2 w0 = unpk(wz_[2 * i]);
                float2 w1 = unpk(wz_[2 * i + 1]);
                float2 v0 = unpk(wr_[2 * i]);
                float2 v1 = unpk(wr_[2 * i + 1]);
                float4 h0 = *(const float4*)&hpre[0][kq][4 * i];
                float4 h1 = *(const float4*)&hpre[1][kq][4 * i];
                float2 lo0 = mk2(h0.x, h0.y), hi0 = mk2(h0.z, h0.w);
                float2 lo1 = mk2(h1.x, h1.y), hi1 = mk2(h1.z, h1.w);
                ffma2(az0, w0, lo0); ffma2(az0, w1, hi0);
                ffma2(az1, w0, lo1); ffma2(az1, w1, hi1);
                ffma2(ar0, v0, lo0); ffma2(ar0, v1, hi0);
                ffma2(ar1, v0, lo1); ffma2(ar1, v1, hi1);
            }
            float zs0 = az0.x + az0.y, zs1 = az1.x + az1.y;
            float rs0 = ar0.x + ar0.y, rs1 = ar1.x + ar1.y;
            zs0 += __shfl_xor_sync(0xFFFFFFFFu, zs0, 1);
            zs0 += __shfl_xor_sync(0xFFFFFFFFu, zs0, 2);
            zs1 += __shfl_xor_sync(0xFFFFFFFFu, zs1, 1);
            zs1 += __shfl_xor_sync(0xFFFFFFFFu, zs1, 2);
            rs0 += __shfl_xor_sync(0xFFFFFFFFu, rs0, 1);
            rs0 += __shfl_xor_sync(0xFFFFFFFFu, rs0, 2);
            rs1 += __shfl_xor_sync(0xFFFFFFFFu, rs1, 1);
            rs1 += __shfl_xor_sync(0xFFFFFFFFu, rs1, 2);
            if (epi) {
                zraw = (kq ? zs1 : zs0) + pz;     // sigmoid deferred to C
                float rp = (kq ? rs1 : rs0) + pr;
                float r  = __fdividef(1.f, 1.f + __expf(-rp));
                crh[kq][j >> 5][j & 31] = r * hown;
            }
        }
        __syncthreads();                                   // bar 1

        // ---- stage C: Wh_h @ (r*hpre), K-quarter kq, both batches ----
        {
            float2 c0 = mk2(0.f,0.f), c1 = mk2(0.f,0.f);
            #pragma unroll
            for (int i = 0; i < 8; ++i) {
                float2 w0 = unpk(wh_[2 * i]);
                float2 w1 = unpk(wh_[2 * i + 1]);
                float4 r0 = *(const float4*)&crh[0][kq][4 * i];
                float4 r1 = *(const float4*)&crh[1][kq][4 * i];
                ffma2(c0, w0, mk2(r0.x, r0.y)); ffma2(c0, w1, mk2(r0.z, r0.w));
                ffma2(c1, w0, mk2(r1.x, r1.y)); ffma2(c1, w1, mk2(r1.z, r1.w));
            }
            float cs0 = c0.x + c0.y, cs1 = c1.x + c1.y;
            cs0 += __shfl_xor_sync(0xFFFFFFFFu, cs0, 1);
            cs0 += __shfl_xor_sync(0xFFFFFFFFu, cs0, 2);
            cs1 += __shfl_xor_sync(0xFFFFFFFFu, cs1, 1);
            cs1 += __shfl_xor_sync(0xFFFFFFFFu, cs1, 2);
            if (epi) {
                float pre = (kq ? cs1 : cs0) + px;
                float zg  = __fdividef(1.f, 1.f + __expf(-zraw));
                float e2  = __expf(2.f * pre);
                float ht  = 1.f - __fdividef(2.f, e2 + 1.f);    // tanh
                float hn  = fmaf(zg, ht - hown, hown);
                out[((size_t)(b0 + kq) * TT + t) * HH + j] = hn;
                float hp = pd * hn;                  // dh(t+1) * h_t
                hown = hp;
                hpre[kq][j >> 5][j & 31] = hp;
                // rotate THEN reload (safe double-buffer: n consumed as p
                // at t+1 was loaded at t-1; reload fills tuple(t+2))
                pz = nz; pr = nr; px = nx; pd = nd;
                int t2 = (t + 2 < TT) ? t + 2 : TT - 1;
                int t3 = (t + 3 < TT) ? t + 3 : TT - 1;
                size_t o = tb + (size_t)t2 * 512;
                nz = g_pre[o];
                nr = g_pre[o + 128];
                nx = g_pre[o + 256];
                nd = g_pre[tb + (size_t)t3 * 512 + 384];
            }
        }
        __syncthreads();                                   // bar 2
    }
}

} // namespace

extern "C" void kernel_launch(void* const* d_in, const int* in_sizes, int n_in,
                              void* d_out, int out_size) {
    const float* inp = (const float*)d_in[0];
    const float* Wgx = (const float*)d_in[1];
    const float* bgx = (const float*)d_in[2];
    const float* Wgh = (const float*)d_in[3];
    const float* bgh = (const float*)d_in[4];
    const float* Wz  = (const float*)d_in[5];
    const float* bz  = (const float*)d_in[6];
    const float* Wr  = (const float*)d_in[7];
    const float* br  = (const float*)d_in[8];
    const float* Wh  = (const float*)d_in[9];
    const float* bh  = (const float*)d_in[10];
    float* out = (float*)d_out;

    act_kernel<<<NROW / 8, 256>>>(inp, Wgx, bgx);
    packw_kernel<<<56, 256>>>(Wz, Wr, Wh, Wgh);
    cudaFuncSetAttribute(gemm_kernel,
                         cudaFuncAttributeMaxDynamicSharedMemorySize, GEMM_SMEM);
    gemm_kernel<<<NROW / 128, 256, GEMM_SMEM>>>(bz, br, bh, bgh);
    scan_kernel<<<BB / 2, 512>>>(Wz, Wr, Wh, out);
}

// round 16
// speedup vs baseline: 1.6629x; 1.6629x over previous
#include <cuda_runtime.h>
#include <cuda_fp16.h>
#include <cstdint>

namespace {

constexpr int BB = 256, TT = 512, DD = 64, HH = 128, KC = 256;
constexpr int NROW = BB * TT;            // 131072 (b,t) rows

// g_pre[row][q][j]: q = 0 zpre(+bz), 1 rpre(+br), 2 xmpre(+bh), 3 dh
__device__ float  g_pre[(size_t)NROW * 4 * HH];            // 256 MB
__device__ __half g_act[(size_t)NROW * 192];               // [row][xt|m|d]
// B fragments in mma.m16n8k16 lane order: 448 frags x 32 lanes x uint2
__device__ uint2  g_wfrag[448 * 32];

__device__ __forceinline__ float2 mk2(float x, float y) { return make_float2(x, y); }

__device__ __forceinline__ unsigned pack_h2(float x, float y) {
    __half2 h = __floats2half2_rn(x, y);
    return *reinterpret_cast<unsigned*>(&h);
}

#define MMA16816(d0, d1, d2, d3, a0, a1, a2, a3, b0, b1)                     \
    asm volatile(                                                            \
        "mma.sync.aligned.m16n8k16.row.col.f32.f16.f16.f32 "                 \
        "{%0,%1,%2,%3}, {%4,%5,%6,%7}, {%8,%9}, {%0,%1,%2,%3};"              \
        : "+f"(d0), "+f"(d1), "+f"(d2), "+f"(d3)                             \
        : "r"(a0), "r"(a1), "r"(a2), "r"(a3), "r"(b0), "r"(b1))

// ===========================================================================
// P1: elementwise -> fp16 act matrix [row][ xt(64) | m(64) | d(64) ].
// ===========================================================================
__global__ void __launch_bounds__(256, 1) act_kernel(
    const float* __restrict__ inp,
    const float* __restrict__ Wgx, const float* __restrict__ bgx)
{
    const int row = blockIdx.x * 8 + (threadIdx.x >> 5);
    const int l   = threadIdx.x & 31;
    const int b = row >> 9, t = row & 511;
    const float* ib = inp + ((long)(b * 4) * TT + t) * DD;
    const long CH = (long)TT * DD;
    float2 x  = *(const float2*)(ib + 2 * l);
    float2 xl = *(const float2*)(ib + CH + 2 * l);
    float2 m  = *(const float2*)(ib + 2 * CH + 2 * l);
    float2 d  = *(const float2*)(ib + 3 * CH + 2 * l);
    float  g0 = __ldg(&Wgx[(2 * l) * DD + 2 * l]);
    float  g1 = __ldg(&Wgx[(2 * l + 1) * DD + 2 * l + 1]);
    float2 bx = *(const float2*)(bgx + 2 * l);
    float dx0 = __expf(-fmaxf(fmaf(d.x, g0, bx.x), 0.f));
    float dx1 = __expf(-fmaxf(fmaf(d.y, g1, bx.y), 0.f));
    float xt0 = m.x * x.x + (1.f - m.x) * (dx0 * xl.x);
    float xt1 = m.y * x.y + (1.f - m.y) * (dx1 * xl.y);
    __half2* ga = (__half2*)(g_act + (size_t)row * 192);
    ga[l]      = __floats2half2_rn(xt0, xt1);
    ga[32 + l] = __floats2half2_rn(m.x, m.y);
    ga[64 + l] = __floats2half2_rn(d.x, d.y);
}

// ===========================================================================
// P0: pack weights into mma B-fragment lane order (verified R11).
// ===========================================================================
__global__ void packw_kernel(const float* __restrict__ Wz,
                             const float* __restrict__ Wr,
                             const float* __restrict__ Wh,
                             const float* __restrict__ Wgh) {
    int idx = blockIdx.x * 256 + threadIdx.x;
    int fragIdx = idx >> 5, lane = idx & 31;
    if (fragIdx >= 448) return;
    int g = lane >> 2, t = lane & 3;
    uint2 v;
    if (fragIdx < 384) {
        int q   = fragIdx >> 7;
        int rem = fragIdx & 127;
        int jt = rem >> 3, kt = rem & 7;
        const float* W = (q == 0) ? Wz : (q == 1) ? Wr : Wh;
        int j = jt * 8 + g, k0 = kt * 16;
        auto src = [&](int k) {
            int col = (k < 64) ? k : k + 128;
            return W[j * KC + col];
        };
        v.x = pack_h2(src(k0 + 2 * t),     src(k0 + 2 * t + 1));
        v.y = pack_h2(src(k0 + 2 * t + 8), src(k0 + 2 * t + 9));
    } else {
        int rem = fragIdx - 384;
        int jt = rem >> 2, kt = rem & 3;
        int j = jt * 8 + g, k0 = kt * 16;
        v.x = pack_h2(Wgh[j * DD + k0 + 2 * t],     Wgh[j * DD + k0 + 2 * t + 1]);
        v.y = pack_h2(Wgh[j * DD + k0 + 2 * t + 8], Wgh[j * DD + k0 + 2 * t + 9]);
    }
    g_wfrag[fragIdx * 32 + lane] = v;
}

// ===========================================================================
// P2: HMMA GEMM (verified R11, ~90 us).
// ===========================================================================
constexpr int GS_ACT  = 0;
constexpr int GS_WF   = 51200;
constexpr int GS_BIAS = GS_WF + 114688;
constexpr int GEMM_SMEM = GS_BIAS + 512 * 4;

__global__ void __launch_bounds__(256, 1) gemm_kernel(
    const float* __restrict__ bz, const float* __restrict__ br,
    const float* __restrict__ bh, const float* __restrict__ bgh)
{
    extern __shared__ char sm[];
    __half* sact = (__half*)(sm + GS_ACT);
    uint2*  swf  = (uint2*)(sm + GS_WF);
    float*  sbias = (float*)(sm + GS_BIAS);

    const int tid = threadIdx.x;
    const int row0 = blockIdx.x * 128;

    for (int i = tid; i < 128 * 48; i += 256) {
        int r = i / 48, c = i - r * 48;
        uint2 v = *(const uint2*)(g_act + (size_t)(row0 + r) * 192 + c * 4);
        *(uint2*)(sact + r * 200 + c * 4) = v;
    }
    for (int i = tid; i < 448 * 32 / 2; i += 256)
        ((uint4*)swf)[i] = ((const uint4*)g_wfrag)[i];
    if (tid < 128) {
        sbias[tid] = bz[tid];       sbias[128 + tid] = br[tid];
        sbias[256 + tid] = bh[tid]; sbias[384 + tid] = bgh[tid];
    }
    __syncthreads();

    const int w = tid >> 5, lane = tid & 31;
    const int g = lane >> 2, t = lane & 3;
    const int arow = w * 16 + g;

    uint32_t A[12][4];
    #pragma unroll
    for (int kt = 0; kt < 12; ++kt) {
        int k0 = (kt < 8) ? kt * 16 : 128 + (kt - 8) * 16;
        const __half* p = sact + arow * 200 + k0 + 2 * t;
        A[kt][0] = *(const uint32_t*)(p);
        A[kt][1] = *(const uint32_t*)(p + 8 * 200);
        A[kt][2] = *(const uint32_t*)(p + 8);
        A[kt][3] = *(const uint32_t*)(p + 8 * 200 + 8);
    }

    for (int q = 0; q < 3; ++q) {
        #pragma unroll 4
        for (int jt = 0; jt < 16; ++jt) {
            float d0 = 0.f, d1 = 0.f, d2 = 0.f, d3 = 0.f;
            const uint2* wp = swf + (q * 128 + jt * 8) * 32 + lane;
            #pragma unroll
            for (int kt = 0; kt < 8; ++kt) {
                uint2 b = wp[kt * 32];
                MMA16816(d0, d1, d2, d3,
                         A[kt][0], A[kt][1], A[kt][2], A[kt][3], b.x, b.y);
            }
            int j0 = jt * 8 + 2 * t;
            float2 bb = *(const float2*)&sbias[q * 128 + j0];
            size_t base = (size_t)(row0 + arow) * 512 + q * 128 + j0;
            *(float2*)&g_pre[base]            = mk2(d0 + bb.x, d1 + bb.y);
            *(float2*)&g_pre[base + 8 * 512]  = mk2(d2 + bb.x, d3 + bb.y);
        }
    }
    #pragma unroll 4
    for (int jt = 0; jt < 16; ++jt) {
        float d0 = 0.f, d1 = 0.f, d2 = 0.f, d3 = 0.f;
        const uint2* wp = swf + (384 + jt * 4) * 32 + lane;
        #pragma unroll
        for (int kt = 0; kt < 4; ++kt) {
            uint2 b = wp[kt * 32];
            MMA16816(d0, d1, d2, d3,
                     A[8 + kt][0], A[8 + kt][1], A[8 + kt][2], A[8 + kt][3],
                     b.x, b.y);
        }
        int j0 = jt * 8 + 2 * t;
        float2 bb = *(const float2*)&sbias[384 + j0];
        size_t base = (size_t)(row0 + arow) * 512 + 384 + j0;
        *(float2*)&g_pre[base] =
            mk2(__expf(-fmaxf(d0 + bb.x, 0.f)), __expf(-fmaxf(d1 + bb.y, 0.f)));
        *(float2*)&g_pre[base + 8 * 512] =
            mk2(__expf(-fmaxf(d2 + bb.x, 0.f)), __expf(-fmaxf(d3 + bb.y, 0.f)));
    }
}

// ===========================================================================
// Scan v7: R10 structure (NT=256, thread=(j,kh), 2 barriers, shfl.xor(1)
// reduce) but GEMV math in HFMA2 on fp16 smem activations:
//   - zero per-step weight conversions (weights stay packed half2)
//   - uint4 activation loads (8 halves) halve LDS request count
//   - fp16 accumulation chunked every 16 terms, flushed to fp32
// ===========================================================================
__global__ void __launch_bounds__(256, 1) scan_kernel(
    const float* __restrict__ Wz, const float* __restrict__ Wr,
    const float* __restrict__ Wh,
    float* __restrict__ out)         // [B,T,H]
{
    // [batch][j-half][64 halves + 8 pad]; (b*2+kh)*144 B base, 16-aligned
    __shared__ __align__(16) __half hpre16[2][2][72];
    __shared__ __align__(16) __half crh16 [2][2][72];

    const int tid = threadIdx.x;
    const int b0  = blockIdx.x * 2;
    const int j   = tid >> 1;        // output row 0..127
    const int kh  = tid & 1;         // K-half (GEMV) / batch (epilogue)

    // ---- persistent packed fp16 weight rows over h-region K-half kh ----
    __half2 wz2[32], wr2[32], wh2[32];
    {
        const int koff = 64 + kh * 64;
        #pragma unroll
        for (int i = 0; i < 32; ++i) {
            float2 a = *(const float2*)&Wz[j * KC + koff + 2 * i];
            wz2[i] = __floats2half2_rn(a.x, a.y);
            float2 b = *(const float2*)&Wr[j * KC + koff + 2 * i];
            wr2[i] = __floats2half2_rn(b.x, b.y);
            float2 c = *(const float2*)&Wh[j * KC + koff + 2 * i];
            wh2[i] = __floats2half2_rn(c.x, c.y);
        }
    }
    for (int i = tid; i < 2 * 2 * 72; i += 256) {
        ((__half*)hpre16)[i] = __float2half(0.f);
        ((__half*)crh16)[i]  = __float2half(0.f);
    }

    // scratch stream (epilogue role: batch kh, row j)
    const size_t tb = ((size_t)(b0 + kh) * TT) * 512 + j;
    float pz, pr, px, pd, nz, nr, nx, nd;
    pz = g_pre[tb];
    pr = g_pre[tb + 128];
    px = g_pre[tb + 256];
    pd = g_pre[tb + 512 + 384];          // dh(1)
    nz = g_pre[tb + 512];
    nr = g_pre[tb + 512 + 128];
    nx = g_pre[tb + 512 + 256];
    nd = g_pre[tb + 1024 + 384];         // dh(2)
    float hown = 0.f, zraw = 0.f;
    __syncthreads();

    const __half2 hz = __float2half2_rn(0.f);

    for (int t = 0; t < TT; ++t) {
        // ---- stage A: z/r over K-half kh, both batches; HFMA2 chunks ----
        {
            float2 AZ0 = mk2(0.f,0.f), AZ1 = mk2(0.f,0.f);
            float2 AR0 = mk2(0.f,0.f), AR1 = mk2(0.f,0.f);
            #pragma unroll
            for (int c = 0; c < 4; ++c) {              // chunk = 16 terms
                __half2 az0 = hz, az1 = hz, ar0 = hz, ar1 = hz;
                #pragma unroll
                for (int u = 0; u < 2; ++u) {
                    const int idx = 2 * c + u;
                    uint4 v0 = *(const uint4*)&hpre16[0][kh][8 * idx];
                    uint4 v1 = *(const uint4*)&hpre16[1][kh][8 * idx];
                    const __half2* p0 = (const __half2*)&v0;
                    const __half2* p1 = (const __half2*)&v1;
                    #pragma unroll
                    for (int q = 0; q < 4; ++q) {
                        az0 = __hfma2(wz2[4 * idx + q], p0[q], az0);
                        az1 = __hfma2(wz2[4 * idx + q], p1[q], az1);
                        ar0 = __hfma2(wr2[4 * idx + q], p0[q], ar0);
                        ar1 = __hfma2(wr2[4 * idx + q], p1[q], ar1);
                    }
                }
                float2 f;
                f = __half22float2(az0); AZ0.x += f.x; AZ0.y += f.y;
                f = __half22float2(az1); AZ1.x += f.x; AZ1.y += f.y;
                f = __half22float2(ar0); AR0.x += f.x; AR0.y += f.y;
                f = __half22float2(ar1); AR1.x += f.x; AR1.y += f.y;
            }
            float zs0 = AZ0.x + AZ0.y, zs1 = AZ1.x + AZ1.y;
            float rs0 = AR0.x + AR0.y, rs1 = AR1.x + AR1.y;
            zs0 += __shfl_xor_sync(0xFFFFFFFFu, zs0, 1);
            zs1 += __shfl_xor_sync(0xFFFFFFFFu, zs1, 1);
            rs0 += __shfl_xor_sync(0xFFFFFFFFu, rs0, 1);
            rs1 += __shfl_xor_sync(0xFFFFFFFFu, rs1, 1);
            zraw = (kh ? zs1 : zs0) + pz;              // sigmoid deferred
            float rp = (kh ? rs1 : rs0) + pr;
            float r  = __fdividef(1.f, 1.f + __expf(-rp));
            crh16[kh][j >> 6][j & 63] = __float2half(r * hown);
        }
        __syncthreads();                                   // bar 1

        // ---- stage C: Wh_h @ (r*hpre), K-half kh, both batches ----
        {
            float2 C0 = mk2(0.f,0.f), C1 = mk2(0.f,0.f);
            #pragma unroll
            for (int c = 0; c < 4; ++c) {
                __half2 a0 = hz, a1 = hz;
                #pragma unroll
                for (int u = 0; u < 2; ++u) {
                    const int idx = 2 * c + u;
                    uint4 v0 = *(const uint4*)&crh16[0][kh][8 * idx];
                    uint4 v1 = *(const uint4*)&crh16[1][kh][8 * idx];
                    const __half2* p0 = (const __half2*)&v0;
                    const __half2* p1 = (const __half2*)&v1;
                    #pragma unroll
                    for (int q = 0; q < 4; ++q) {
                        a0 = __hfma2(wh2[4 * idx + q], p0[q], a0);
                        a1 = __hfma2(wh2[4 * idx + q], p1[q], a1);
                    }
                }
                float2 f;
                f = __half22float2(a0); C0.x += f.x; C0.y += f.y;
                f = __half22float2(a1); C1.x += f.x; C1.y += f.y;
            }
            float cs0 = C0.x + C0.y, cs1 = C1.x + C1.y;
            cs0 += __shfl_xor_sync(0xFFFFFFFFu, cs0, 1);
            cs1 += __shfl_xor_sync(0xFFFFFFFFu, cs1, 1);
            float pre = (kh ? cs1 : cs0) + px;
            float zg  = __fdividef(1.f, 1.f + __expf(-zraw));
            float e2  = __expf(2.f * pre);
            float ht  = 1.f - __fdividef(2.f, e2 + 1.f);       // tanh
            float hn  = fmaf(zg, ht - hown, hown);
            out[((size_t)(b0 + kh) * TT + t) * HH + j] = hn;
            float hp = pd * hn;                    // dh(t+1) * h_t
            hown = hp;
            hpre16[kh][j >> 6][j & 63] = __float2half(hp);
            // rotate THEN reload (verified-safe double buffer from R15)
            pz = nz; pr = nr; px = nx; pd = nd;
            int t2 = (t + 2 < TT) ? t + 2 : TT - 1;
            int t3 = (t + 3 < TT) ? t + 3 : TT - 1;
            size_t o = tb + (size_t)t2 * 512;
            nz = g_pre[o];
            nr = g_pre[o + 128];
            nx = g_pre[o + 256];
            nd = g_pre[tb + (size_t)t3 * 512 + 384];
        }
        __syncthreads();                                   // bar 2
    }
}

} // namespace

extern "C" void kernel_launch(void* const* d_in, const int* in_sizes, int n_in,
                              void* d_out, int out_size) {
    const float* inp = (const float*)d_in[0];
    const float* Wgx = (const float*)d_in[1];
    const float* bgx = (const float*)d_in[2];
    const float* Wgh = (const float*)d_in[3];
    const float* bgh = (const float*)d_in[4];
    const float* Wz  = (const float*)d_in[5];
    const float* bz  = (const float*)d_in[6];
    const float* Wr  = (const float*)d_in[7];
    const float* br  = (const float*)d_in[8];
    const float* Wh  = (const float*)d_in[9];
    const float* bh  = (const float*)d_in[10];
    float* out = (float*)d_out;

    act_kernel<<<NROW / 8, 256>>>(inp, Wgx, bgx);
    packw_kernel<<<56, 256>>>(Wz, Wr, Wh, Wgh);
    cudaFuncSetAttribute(gemm_kernel,
                         cudaFuncAttributeMaxDynamicSharedMemorySize, GEMM_SMEM);
    gemm_kernel<<<NROW / 128, 256, GEMM_SMEM>>>(bz, br, bh, bgh);
    scan_kernel<<<BB / 2, 256>>>(Wz, Wr, Wh, out);
}